// round 1
// baseline (speedup 1.0000x reference)
#include <cuda_runtime.h>
#include <math.h>

// Problem constants (fixed shapes from setup_inputs)
#define NN    64
#define CC    128
#define KK    64
#define PP    4096
#define PBLK  256     // pixels per block
#define CHUNK 128     // pixels per inner chunk
#define NCHUNK (PBLK / CHUNK)
#define SX    132     // xs row stride (floats), pad for bank behavior
#define SA    132     // at row stride (floats)

typedef unsigned long long u64;

__device__ __forceinline__ u64 fma2(u64 a, u64 b, u64 c) {
    u64 d;
    asm("fma.rn.f32x2 %0, %1, %2, %3;" : "=l"(d) : "l"(a), "l"(b), "l"(c));
    return d;
}
__device__ __forceinline__ u64 pack2(float lo, float hi) {
    u64 d;
    asm("mov.b64 %0, {%1, %2};" : "=l"(d) : "f"(lo), "f"(hi));
    return d;
}
__device__ __forceinline__ float2 unpack2(u64 v) {
    float2 r;
    asm("mov.b64 {%0, %1}, %2;" : "=f"(r.x), "=f"(r.y) : "l"(v));
    return r;
}

// Scratch accumulators (device globals: no cudaMalloc allowed)
__device__ float g_vacc[NN * KK * CC];   // 2 MB
__device__ float g_sacc[NN * KK];

__global__ void zero_kernel() {
    int i = blockIdx.x * blockDim.x + threadIdx.x;
    if (i < NN * KK * CC) g_vacc[i] = 0.0f;
    if (i < NN * KK)      g_sacc[i] = 0.0f;
}

// Fused: logits GEMM -> softmax -> assignment GEMM, partials into g_vacc/g_sacc
__global__ __launch_bounds__(256, 1)
void netvlad_main(const float* __restrict__ x,
                  const float* __restrict__ w,
                  const float* __restrict__ bias) {
    extern __shared__ float sm[];
    float* Wd   = sm;                    // [128][128] : Wd[c*128 + 2k] = {w,w} duplicated pairs
    float* xs   = Wd + CC * CC;          // [128][SX]  : x chunk, channel-major
    float* at   = xs + CC * SX;          // [64][SA]   : logits -> softmax a, k-major
    float* redm = at + KK * SA;          // [2][128]
    float* reds = redm + 2 * CHUNK;      // [2][128]

    const int tid  = threadIdx.x;
    const int lane = tid & 31;
    const int warp = tid >> 5;
    const int n  = blockIdx.y;
    const int pb = blockIdx.x;

    // Load W with duplicated pairs: Wd[c][2k..2k+1] = conv_w[k][c]
    for (int idx = tid; idx < KK * CC; idx += 256) {
        int k = idx >> 7, c = idx & 127;
        float v = w[idx];
        Wd[c * CC + 2 * k]     = v;
        Wd[c * CC + 2 * k + 1] = v;
    }

    // Bias pairs for stage1 (k range of this warp)
    u64 bj[8];
#pragma unroll
    for (int j = 0; j < 8; ++j) {
        float bv = bias[8 * warp + j];
        bj[j] = pack2(bv, bv);
    }

    // Stage2 accumulators: accv[j][i] packed over p-parity; k = (lane&7)+8j, c = cbase+i
    u64 accv[8][4];
#pragma unroll
    for (int j = 0; j < 8; ++j)
#pragma unroll
        for (int i = 0; i < 4; ++i) accv[j][i] = 0ull;

    float asum_loc = 0.0f;

    const float* xg_n = x + (size_t)n * CC * PP + (size_t)pb * PBLK;
    const int kg2   = lane & 7;
    const int cbase = 16 * warp + 4 * (lane >> 3);

    for (int ch = 0; ch < NCHUNK; ++ch) {
        __syncthreads();   // prior stage2 must finish before xs overwrite

        // ---- load x chunk: xs[c][p], coalesced float4 ----
        const float* xg = xg_n + ch * CHUNK;
        for (int i4 = tid; i4 < (CC * CHUNK) / 4; i4 += 256) {
            int c  = i4 >> 5;
            int p4 = (i4 & 31) << 2;
            float4 v = *reinterpret_cast<const float4*>(xg + (size_t)c * PP + p4);
            *reinterpret_cast<float4*>(&xs[c * SX + p4]) = v;
        }
        __syncthreads();

        // ---- stage1: logits[k][p] for k in [8*warp,+8), p in [4*lane,+4) ----
        {
            u64 l01[8], l23[8];
#pragma unroll
            for (int j = 0; j < 8; ++j) { l01[j] = bj[j]; l23[j] = bj[j]; }
            const float* xrow = &xs[4 * lane];
            const float* wrow = &Wd[16 * warp];
#pragma unroll 2
            for (int c = 0; c < CC; ++c) {
                ulonglong2 xq = *reinterpret_cast<const ulonglong2*>(xrow + c * SX);
#pragma unroll
                for (int jj = 0; jj < 4; ++jj) {
                    ulonglong2 wq = *reinterpret_cast<const ulonglong2*>(wrow + c * CC + 4 * jj);
                    l01[2 * jj]     = fma2(wq.x, xq.x, l01[2 * jj]);
                    l23[2 * jj]     = fma2(wq.x, xq.y, l23[2 * jj]);
                    l01[2 * jj + 1] = fma2(wq.y, xq.x, l01[2 * jj + 1]);
                    l23[2 * jj + 1] = fma2(wq.y, xq.y, l23[2 * jj + 1]);
                }
            }
#pragma unroll
            for (int j = 0; j < 8; ++j) {
                float2 a = unpack2(l01[j]);
                float2 b = unpack2(l23[j]);
                *reinterpret_cast<float4*>(&at[(8 * warp + j) * SA + 4 * lane]) =
                    make_float4(a.x, a.y, b.x, b.y);
            }
        }
        __syncthreads();

        // ---- softmax over k per pixel (2 threads per pixel) ----
        {
            int p = tid & 127, h = tid >> 7;
            int k0 = 32 * h;
            float m = -1e30f;
            for (int k = k0; k < k0 + 32; ++k) m = fmaxf(m, at[k * SA + p]);
            redm[h * CHUNK + p] = m;
            __syncthreads();
            float M = fmaxf(redm[p], redm[CHUNK + p]);
            float s = 0.0f;
            for (int k = k0; k < k0 + 32; ++k) {
                float e = __expf(at[k * SA + p] - M);
                at[k * SA + p] = e;
                s += e;
            }
            reds[h * CHUNK + p] = s;
            __syncthreads();
            float inv = 1.0f / (reds[p] + reds[CHUNK + p]);
            for (int k = k0; k < k0 + 32; ++k) at[k * SA + p] *= inv;
        }
        __syncthreads();

        // ---- a_sum per k (threads 0..63) ----
        if (tid < KK) {
            float s = 0.0f;
#pragma unroll 4
            for (int p = 0; p < CHUNK; ++p) s += at[tid * SA + p];
            asum_loc += s;
        }

        // ---- stage2: V[k][c] += sum_p a[k][p] * x[c][p], packed over p parity ----
        for (int p4 = 0; p4 < CHUNK; p4 += 4) {
            ulonglong2 xq0 = *reinterpret_cast<const ulonglong2*>(&xs[(cbase + 0) * SX + p4]);
            ulonglong2 xq1 = *reinterpret_cast<const ulonglong2*>(&xs[(cbase + 1) * SX + p4]);
            ulonglong2 xq2 = *reinterpret_cast<const ulonglong2*>(&xs[(cbase + 2) * SX + p4]);
            ulonglong2 xq3 = *reinterpret_cast<const ulonglong2*>(&xs[(cbase + 3) * SX + p4]);
#pragma unroll
            for (int j = 0; j < 8; ++j) {
                ulonglong2 aq = *reinterpret_cast<const ulonglong2*>(&at[(kg2 + 8 * j) * SA + p4]);
                accv[j][0] = fma2(aq.x, xq0.x, accv[j][0]);
                accv[j][0] = fma2(aq.y, xq0.y, accv[j][0]);
                accv[j][1] = fma2(aq.x, xq1.x, accv[j][1]);
                accv[j][1] = fma2(aq.y, xq1.y, accv[j][1]);
                accv[j][2] = fma2(aq.x, xq2.x, accv[j][2]);
                accv[j][2] = fma2(aq.y, xq2.y, accv[j][2]);
                accv[j][3] = fma2(aq.x, xq3.x, accv[j][3]);
                accv[j][3] = fma2(aq.y, xq3.y, accv[j][3]);
            }
        }
    }

    // ---- write partials ----
#pragma unroll
    for (int j = 0; j < 8; ++j) {
        int k = kg2 + 8 * j;
#pragma unroll
        for (int i = 0; i < 4; ++i) {
            float2 v = unpack2(accv[j][i]);
            atomicAdd(&g_vacc[((size_t)n * KK + k) * CC + cbase + i], v.x + v.y);
        }
    }
    if (tid < KK) atomicAdd(&g_sacc[n * KK + tid], asum_loc);
}

// Finalize: v = vacc - asum*centroid, intra-cluster L2 norm, global L2 norm
__global__ __launch_bounds__(256)
void netvlad_final(const float* __restrict__ cent, float* __restrict__ out) {
    __shared__ float ybuf[KK * CC];   // 32 KB
    __shared__ float asum_s[KK];
    __shared__ float gred[8];

    int n = blockIdx.x, tid = threadIdx.x, lane = tid & 31, warp = tid >> 5;
    if (tid < KK) asum_s[tid] = g_sacc[n * KK + tid];
    __syncthreads();

    float gw = 0.0f;
    for (int kk = 0; kk < 8; ++kk) {
        int k = 8 * kk + warp;
        float4 va = *reinterpret_cast<const float4*>(&g_vacc[((size_t)n * KK + k) * CC + 4 * lane]);
        float4 ce = *reinterpret_cast<const float4*>(&cent[k * CC + 4 * lane]);
        float as = asum_s[k];
        float v0 = va.x - as * ce.x;
        float v1 = va.y - as * ce.y;
        float v2 = va.z - as * ce.z;
        float v3 = va.w - as * ce.w;
        float ssq = v0 * v0 + v1 * v1 + v2 * v2 + v3 * v3;
#pragma unroll
        for (int o = 16; o; o >>= 1) ssq += __shfl_xor_sync(0xffffffffu, ssq, o);
        float rn = 1.0f / fmaxf(sqrtf(ssq), 1e-12f);
        *reinterpret_cast<float4*>(&ybuf[k * CC + 4 * lane]) =
            make_float4(v0 * rn, v1 * rn, v2 * rn, v3 * rn);
        gw += ssq * rn * rn;
    }
    if (lane == 0) gred[warp] = gw;
    __syncthreads();
    if (tid == 0) {
        float g = 0.0f;
        for (int i = 0; i < 8; ++i) g += gred[i];
        gred[0] = 1.0f / fmaxf(sqrtf(g), 1e-12f);
    }
    __syncthreads();
    float rg = gred[0];
    for (int i4 = tid; i4 < (KK * CC) / 4; i4 += 256) {
        float4 y = *reinterpret_cast<const float4*>(&ybuf[4 * i4]);
        *reinterpret_cast<float4*>(&out[(size_t)n * KK * CC + 4 * i4]) =
            make_float4(y.x * rg, y.y * rg, y.z * rg, y.w * rg);
    }
}

#define SMEM_BYTES ((CC * CC + CC * SX + KK * SA + 4 * CHUNK) * (int)sizeof(float))

extern "C" void kernel_launch(void* const* d_in, const int* in_sizes, int n_in,
                              void* d_out, int out_size) {
    const float* x    = (const float*)d_in[0];
    const float* w    = (const float*)d_in[1];
    const float* b    = (const float*)d_in[2];
    const float* cent = (const float*)d_in[3];
    float* out = (float*)d_out;
    (void)in_sizes; (void)n_in; (void)out_size;

    cudaFuncSetAttribute(netvlad_main, cudaFuncAttributeMaxDynamicSharedMemorySize, SMEM_BYTES);

    zero_kernel<<<(NN * KK * CC + 255) / 256, 256>>>();
    netvlad_main<<<dim3(PP / PBLK, NN), 256, SMEM_BYTES>>>(x, w, b);
    netvlad_final<<<NN, 256>>>(cent, out);
}

// round 10
// speedup vs baseline: 2.9414x; 2.9414x over previous
#include <cuda_runtime.h>
#include <cstdint>
#include <math.h>

// ---------------- problem constants ----------------
#define NN 64
#define CC 128          // channels
#define KK 64           // clusters
#define PP 4096         // pixels per image
#define PT 128          // pixels per chunk
#define HALVES 2
#define P_HALF (PP / HALVES)
#define NCHUNK (P_HALF / PT)   // 16

// smem strides (floats) — bank-conflict audited
#define SLW  132   // W  [k][c]   stage1-A lanes (4g+m) unique
#define SLX1 132   // x  [c][p]   stage2-A lanes (4g+m) unique
#define SLX2 136   // x  [c][p]   stage1-B lanes (8m+g) unique
#define SLA  132   // a  [k][p]   softmax p-lanes + stage2-B (4g+m) unique

// smem layout (float offsets)
#define W_OFF   0
#define X1_OFF  (W_OFF + KK * SLW)       // 8448
#define X2_OFF  (X1_OFF + CC * SLX1)     // 25344
#define A_OFF   (X2_OFF + CC * SLX2)     // 42752
#define RM_OFF  (A_OFF + KK * SLA)       // 51200
#define RS_OFF  (RM_OFF + 2 * PT)        // 51456
#define B_OFF   (RS_OFF + 2 * PT)        // 51712
#define SMEM_FLOATS (B_OFF + KK)         // 51776
#define SMEM_BYTES  (SMEM_FLOATS * 4)    // 207104 B

// ---------------- scratch (device globals: no cudaMalloc) ----------------
__device__ float g_vacc[NN * HALVES * KK * CC];  // 4 MB, written once
__device__ float g_sacc[NN * HALVES * KK];

// ---------------- helpers ----------------
__device__ __forceinline__ float to_tf32(float x) {
    float r; asm("cvt.rna.tf32.f32 %0, %1;" : "=f"(r) : "f"(x)); return r;
}
__device__ __forceinline__ uint32_t f2u(float f) { return __float_as_uint(f); }

// m16n8k8 tf32 MMA. Fragment layout (PTX doc, g=lane>>2, m=lane&3):
//   A: a0=(g, m) a1=(g+8, m) a2=(g, m+4) a3=(g+8, m+4)   [16x8 row-major]
//   B: b0=(m, g) b1=(m+4, g)                             [8x8  col-major]
//   D: c0=(g,2m) c1=(g,2m+1) c2=(g+8,2m) c3=(g+8,2m+1)
__device__ __forceinline__ void mma8(float d[4], uint32_t a0, uint32_t a1,
                                     uint32_t a2, uint32_t a3,
                                     uint32_t b0, uint32_t b1) {
    asm volatile(
        "mma.sync.aligned.m16n8k8.row.col.f32.tf32.tf32.f32 "
        "{%0,%1,%2,%3}, {%4,%5,%6,%7}, {%8,%9}, {%0,%1,%2,%3};"
        : "+f"(d[0]), "+f"(d[1]), "+f"(d[2]), "+f"(d[3])
        : "r"(a0), "r"(a1), "r"(a2), "r"(a3), "r"(b0), "r"(b1));
}

// ---------------- main fused kernel ----------------
__global__ __launch_bounds__(256, 1)
void netvlad_main(const float* __restrict__ x,
                  const float* __restrict__ w,
                  const float* __restrict__ bias) {
    extern __shared__ float smf[];
    float* Ws = smf + W_OFF;
    float* X1 = smf + X1_OFF;
    float* X2 = smf + X2_OFF;
    float* As = smf + A_OFF;
    float* redm = smf + RM_OFF;
    float* reds = smf + RS_OFF;
    float* bs   = smf + B_OFF;

    const int tid = threadIdx.x, lane = tid & 31, wq = tid >> 5;
    const int g = lane >> 2, m = lane & 3;
    const int n = blockIdx.y, half = blockIdx.x;

    // ---- load W (tf32-rounded) + bias to smem ----
    for (int i = tid; i < KK * CC; i += 256) {
        int k = i >> 7, c = i & 127;
        Ws[k * SLW + c] = to_tf32(w[i]);
    }
    if (tid < KK) bs[tid] = bias[tid];
    __syncthreads();

    // stage1 warp tiling: 2 m-tiles (k) x 4 n-tiles (p)
    const int mb1 = wq & 1;            // k block
    const int nb1 = (wq >> 1) * 32;    // p block
    // stage2 warp tiling: 4 m-tiles (c) x 2 n-tiles (k)
    const int mb2 = wq & 3;            // c block
    const int nb2 = (wq >> 2) * 32;    // k block

    // bias per C-frag row
    float bl[2], bh[2];
#pragma unroll
    for (int mi = 0; mi < 2; ++mi) {
        bl[mi] = bs[32 * mb1 + 16 * mi + g];
        bh[mi] = bs[32 * mb1 + 16 * mi + g + 8];
    }

    // stage2 accumulators (persist across chunks)
    float accv[2][4][4];
#pragma unroll
    for (int mi = 0; mi < 2; ++mi)
#pragma unroll
        for (int t = 0; t < 4; ++t)
#pragma unroll
            for (int i = 0; i < 4; ++i) accv[mi][t][i] = 0.0f;

    float asum_loc = 0.0f;

    const float* xg = x + (size_t)n * CC * PP + (size_t)half * P_HALF;

    // FULL-chunk register prefetch: 16 float4/thread = 4096 float4 = 128x128
    float4 pf[16];
#pragma unroll
    for (int j = 0; j < 16; ++j) {
        int i = tid + 256 * j;
        pf[j] = *(const float4*)(xg + (size_t)(i >> 5) * PP + ((i & 31) << 2));
    }

    for (int ch = 0; ch < NCHUNK; ++ch) {
        __syncthreads();  // prev stage2 done reading X/As

        // ---- stage x chunk into both smem copies (tf32-rounded) ----
#pragma unroll
        for (int j = 0; j < 16; ++j) {
            int i = tid + 256 * j;
            int c = i >> 5, p4 = (i & 31) << 2;
            float4 v = pf[j];
            v.x = to_tf32(v.x); v.y = to_tf32(v.y);
            v.z = to_tf32(v.z); v.w = to_tf32(v.w);
            *(float4*)(X1 + c * SLX1 + p4) = v;
            *(float4*)(X2 + c * SLX2 + p4) = v;
        }
        // prefetch next chunk (lands while this chunk computes)
        if (ch + 1 < NCHUNK) {
#pragma unroll
            for (int j = 0; j < 16; ++j) {
                int i = tid + 256 * j;
                pf[j] = *(const float4*)(xg + (size_t)(i >> 5) * PP +
                                         (ch + 1) * PT + ((i & 31) << 2));
            }
        }
        __syncthreads();

        // ---- stage1: logits[k][p] = W @ x  (K = c, 16 k8-steps) ----
        {
            float acc1[2][4][4];
#pragma unroll
            for (int mi = 0; mi < 2; ++mi)
#pragma unroll
                for (int t = 0; t < 4; ++t) {
                    acc1[mi][t][0] = bl[mi]; acc1[mi][t][1] = bl[mi];
                    acc1[mi][t][2] = bh[mi]; acc1[mi][t][3] = bh[mi];
                }
            const float* wb = Ws + (32 * mb1 + g) * SLW + m;
#pragma unroll 4
            for (int Ks = 0; Ks < 16; ++Ks) {
                uint32_t aA[2][4];
#pragma unroll
                for (int mi = 0; mi < 2; ++mi) {
                    const float* wp = wb + mi * 16 * SLW + 8 * Ks;
                    aA[mi][0] = f2u(wp[0]);             // (g,   m)
                    aA[mi][1] = f2u(wp[8 * SLW]);       // (g+8, m)
                    aA[mi][2] = f2u(wp[4]);             // (g,   m+4)
                    aA[mi][3] = f2u(wp[8 * SLW + 4]);   // (g+8, m+4)
                }
                const float* xb = X2 + (8 * Ks + m) * SLX2 + nb1 + g;
#pragma unroll
                for (int t = 0; t < 4; ++t) {
                    uint32_t b0 = f2u(xb[8 * t]);               // (m,   g)
                    uint32_t b1 = f2u(xb[4 * SLX2 + 8 * t]);    // (m+4, g)
                    mma8(acc1[0][t], aA[0][0], aA[0][1], aA[0][2], aA[0][3], b0, b1);
                    mma8(acc1[1][t], aA[1][0], aA[1][1], aA[1][2], aA[1][3], b0, b1);
                }
            }
            // store logits to As[k][p] (STS.64 pairs)
#pragma unroll
            for (int mi = 0; mi < 2; ++mi) {
                float* lb = As + (32 * mb1 + 16 * mi + g) * SLA + nb1 + 2 * m;
#pragma unroll
                for (int t = 0; t < 4; ++t) {
                    *(float2*)(lb + 8 * t) =
                        make_float2(acc1[mi][t][0], acc1[mi][t][1]);
                    *(float2*)(lb + 8 * SLA + 8 * t) =
                        make_float2(acc1[mi][t][2], acc1[mi][t][3]);
                }
            }
        }
        __syncthreads();

        // ---- softmax over k, in place (2 threads per pixel) ----
        {
            int p = tid & 127, h = tid >> 7, k0 = h << 5;
            float l[32], mx = -1e30f;
#pragma unroll
            for (int j = 0; j < 32; ++j) {
                l[j] = As[(k0 + j) * SLA + p];
                mx = fmaxf(mx, l[j]);
            }
            redm[h * PT + p] = mx;
            __syncthreads();
            float M = fmaxf(redm[p], redm[PT + p]);
            float s = 0.0f;
#pragma unroll
            for (int j = 0; j < 32; ++j) {
                l[j] = __expf(l[j] - M);
                s += l[j];
            }
            reds[h * PT + p] = s;
            __syncthreads();
            float inv = 1.0f / (reds[p] + reds[PT + p]);
#pragma unroll
            for (int j = 0; j < 32; ++j)
                As[(k0 + j) * SLA + p] = to_tf32(l[j] * inv);
        }
        __syncthreads();

        // ---- asum[k]: warps 0-1, k = tid, conflict-free row reads ----
        // (warps 2-7 fall through to stage2 immediately)
        if (tid < KK) {
            const float4* ap = (const float4*)(As + tid * SLA);
            float s = 0.0f;
#pragma unroll
            for (int j = 0; j < 32; ++j) {
                float4 v = ap[j];
                s += (v.x + v.y) + (v.z + v.w);
            }
            asum_loc += s;
        }

        // ---- stage2: vlad[c][k] += x @ a^T  (K = p, 16 k8-steps) ----
        {
            const float* xb = X1 + (32 * mb2 + g) * SLX1 + m;
            const float* ab = As + (nb2 + g) * SLA + m;
#pragma unroll 4
            for (int Ks = 0; Ks < 16; ++Ks) {
                uint32_t aX[2][4];
#pragma unroll
                for (int mi = 0; mi < 2; ++mi) {
                    const float* xp = xb + mi * 16 * SLX1 + 8 * Ks;
                    aX[mi][0] = f2u(xp[0]);
                    aX[mi][1] = f2u(xp[8 * SLX1]);
                    aX[mi][2] = f2u(xp[4]);
                    aX[mi][3] = f2u(xp[8 * SLX1 + 4]);
                }
#pragma unroll
                for (int t = 0; t < 4; ++t) {
                    uint32_t b0 = f2u(ab[8 * t * SLA + 8 * Ks]);
                    uint32_t b1 = f2u(ab[8 * t * SLA + 8 * Ks + 4]);
                    mma8(accv[0][t], aX[0][0], aX[0][1], aX[0][2], aX[0][3], b0, b1);
                    mma8(accv[1][t], aX[1][0], aX[1][1], aX[1][2], aX[1][3], b0, b1);
                }
            }
        }
    }

    // ---- epilogue: write vlad partials + asum ----
    float* dst = g_vacc + (size_t)(n * HALVES + half) * KK * CC;
#pragma unroll
    for (int mi = 0; mi < 2; ++mi) {
#pragma unroll
        for (int t = 0; t < 4; ++t) {
            int c = 32 * mb2 + 16 * mi + g;
            int k = nb2 + 8 * t + 2 * m;
            dst[k * CC + c]           = accv[mi][t][0];
            dst[(k + 1) * CC + c]     = accv[mi][t][1];
            dst[k * CC + c + 8]       = accv[mi][t][2];
            dst[(k + 1) * CC + c + 8] = accv[mi][t][3];
        }
    }
    if (tid < KK)
        g_sacc[(n * HALVES + half) * KK + tid] = asum_loc;
}

// ---------------- finalize: centroid subtract + intra + global L2 norm ----
__global__ __launch_bounds__(256)
void netvlad_final(const float* __restrict__ cent, float* __restrict__ out) {
    __shared__ float ybuf[KK * CC];
    __shared__ float asum_s[KK];
    __shared__ float gred[8];

    int n = blockIdx.x, tid = threadIdx.x, lane = tid & 31, warp = tid >> 5;
    if (tid < KK)
        asum_s[tid] = g_sacc[(n * HALVES + 0) * KK + tid] +
                      g_sacc[(n * HALVES + 1) * KK + tid];
    __syncthreads();

    const float* v0 = g_vacc + (size_t)(n * HALVES + 0) * KK * CC;
    const float* v1 = g_vacc + (size_t)(n * HALVES + 1) * KK * CC;

    float gw = 0.0f;
    for (int kk = 0; kk < 8; ++kk) {
        int k = 8 * kk + warp;
        float4 a0 = *(const float4*)(v0 + k * CC + 4 * lane);
        float4 a1 = *(const float4*)(v1 + k * CC + 4 * lane);
        float4 ce = *(const float4*)(cent + k * CC + 4 * lane);
        float as = asum_s[k];
        float w0 = a0.x + a1.x - as * ce.x;
        float w1 = a0.y + a1.y - as * ce.y;
        float w2 = a0.z + a1.z - as * ce.z;
        float w3 = a0.w + a1.w - as * ce.w;
        float ssq = w0 * w0 + w1 * w1 + w2 * w2 + w3 * w3;
#pragma unroll
        for (int o = 16; o; o >>= 1) ssq += __shfl_xor_sync(0xffffffffu, ssq, o);
        float rn = 1.0f / fmaxf(sqrtf(ssq), 1e-12f);
        *(float4*)(&ybuf[k * CC + 4 * lane]) =
            make_float4(w0 * rn, w1 * rn, w2 * rn, w3 * rn);
        gw += ssq * rn * rn;
    }
    if (lane == 0) gred[warp] = gw;
    __syncthreads();
    if (tid == 0) {
        float gg = 0.0f;
        for (int i = 0; i < 8; ++i) gg += gred[i];
        gred[0] = 1.0f / fmaxf(sqrtf(gg), 1e-12f);
    }
    __syncthreads();
    float rg = gred[0];
    for (int i4 = tid; i4 < (KK * CC) / 4; i4 += 256) {
        float4 y = *(const float4*)(&ybuf[4 * i4]);
        *(float4*)(&out[(size_t)n * KK * CC + 4 * i4]) =
            make_float4(y.x * rg, y.y * rg, y.z * rg, y.w * rg);
    }
}

extern "C" void kernel_launch(void* const* d_in, const int* in_sizes, int n_in,
                              void* d_out, int out_size) {
    const float* x    = (const float*)d_in[0];
    const float* w    = (const float*)d_in[1];
    const float* b    = (const float*)d_in[2];
    const float* cent = (const float*)d_in[3];
    float* out = (float*)d_out;
    (void)in_sizes; (void)n_in; (void)out_size;

    cudaFuncSetAttribute(netvlad_main, cudaFuncAttributeMaxDynamicSharedMemorySize,
                         SMEM_BYTES);

    netvlad_main<<<dim3(HALVES, NN), 256, SMEM_BYTES>>>(x, w, b);
    netvlad_final<<<NN, 256>>>(cent, out);
}

// round 12
// speedup vs baseline: 3.3376x; 1.1347x over previous
#include <cuda_runtime.h>
#include <cstdint>
#include <math.h>

// ---------------- problem constants ----------------
#define NN 64
#define CC 128          // channels
#define KK 64           // clusters
#define PP 4096         // pixels per image
#define PT 128          // pixels per chunk
#define HALVES 2
#define P_HALF (PP / HALVES)
#define NCHUNK (P_HALF / PT)   // 16

// smem strides (floats) — bank-conflict audited
#define SLW  132   // W  [k][c]   stage1-A lanes (4g+m) unique
#define SLX  140   // x  [c][p]   140%32=12: stage1-B (12m+g) AND stage2-A (12g+m) unique
#define SLA  132   // a  [k][p]   softmax p-lanes + stage2-B (4g+m) unique

// smem layout (float offsets)
#define W_OFF   0
#define A_OFF   (W_OFF + KK * SLW)        // 8448
#define RM_OFF  (A_OFF + KK * SLA)        // 16896
#define RS_OFF  (RM_OFF + 2 * PT)         // 17152
#define B_OFF   (RS_OFF + 2 * PT)         // 17408
#define X0_OFF  (B_OFF + KK)              // 17472
#define X1_OFF  (X0_OFF + CC * SLX)       // 35392
#define SMEM_FLOATS (X1_OFF + CC * SLX)   // 53312
#define SMEM_BYTES  (SMEM_FLOATS * 4)     // 213248 B

// ---------------- scratch (device globals: no cudaMalloc) ----------------
__device__ float g_vacc[NN * HALVES * KK * CC];  // 4 MB
__device__ float g_sacc[NN * HALVES * KK];
__device__ float g_ssq[NN * KK];                 // per-(n,k) intra-norm ssq

// ---------------- helpers ----------------
__device__ __forceinline__ float to_tf32(float x) {
    float r; asm("cvt.rna.tf32.f32 %0, %1;" : "=f"(r) : "f"(x)); return r;
}
__device__ __forceinline__ uint32_t f2u(float f) { return __float_as_uint(f); }

__device__ __forceinline__ uint32_t smem_u32(const void* p) {
    uint32_t a;
    asm("{ .reg .u64 t; cvta.to.shared.u64 t, %1; cvt.u32.u64 %0, t; }"
        : "=r"(a) : "l"(p));
    return a;
}
__device__ __forceinline__ void cp_async16(uint32_t dst, const void* src) {
    asm volatile("cp.async.cg.shared.global [%0], [%1], 16;"
                 :: "r"(dst), "l"(src));
}
__device__ __forceinline__ void cp_commit() {
    asm volatile("cp.async.commit_group;");
}
template <int N>
__device__ __forceinline__ void cp_wait() {
    asm volatile("cp.async.wait_group %0;" :: "n"(N));
}

// m16n8k8 tf32 MMA (fragment layout verified in Round 6+)
__device__ __forceinline__ void mma8(float d[4], uint32_t a0, uint32_t a1,
                                     uint32_t a2, uint32_t a3,
                                     uint32_t b0, uint32_t b1) {
    asm volatile(
        "mma.sync.aligned.m16n8k8.row.col.f32.tf32.tf32.f32 "
        "{%0,%1,%2,%3}, {%4,%5,%6,%7}, {%8,%9}, {%0,%1,%2,%3};"
        : "+f"(d[0]), "+f"(d[1]), "+f"(d[2]), "+f"(d[3])
        : "r"(a0), "r"(a1), "r"(a2), "r"(a3), "r"(b0), "r"(b1));
}

// ---------------- main fused kernel ----------------
__global__ __launch_bounds__(256, 1)
void netvlad_main(const float* __restrict__ x,
                  const float* __restrict__ w,
                  const float* __restrict__ bias) {
    extern __shared__ float smf[];
    float* Ws = smf + W_OFF;
    float* As = smf + A_OFF;
    float* redm = smf + RM_OFF;
    float* reds = smf + RS_OFF;
    float* bs   = smf + B_OFF;

    const int tid = threadIdx.x, lane = tid & 31, wq = tid >> 5;
    const int g = lane >> 2, m = lane & 3;
    const int n = blockIdx.y, half = blockIdx.x;

    // cp.async destination bases (u32 shared addresses)
    const uint32_t xbuf_u32[2] = { smem_u32(smf + X0_OFF), smem_u32(smf + X1_OFF) };

    // ---- load W (tf32-rounded) + bias to smem ----
    for (int i = tid; i < KK * CC; i += 256) {
        int k = i >> 7, c = i & 127;
        Ws[k * SLW + c] = to_tf32(w[i]);
    }
    if (tid < KK) bs[tid] = bias[tid];

    const float* xg = x + (size_t)n * CC * PP + (size_t)half * P_HALF;

    // issue async copy of chunk 0 (16 x 16B per thread; c = i>>5, 32 segs/row)
    {
        uint32_t dst = xbuf_u32[0];
#pragma unroll
        for (int j = 0; j < 16; ++j) {
            int i = tid + 256 * j;
            int c = i >> 5, s16 = i & 31;
            cp_async16(dst + (uint32_t)(c * SLX * 4 + s16 * 16),
                       xg + (size_t)c * PP + s16 * 4);
        }
        cp_commit();
    }

    // stage1 warp tiling: 2 m-tiles (k) x 4 n-tiles (p)
    const int mb1 = wq & 1;
    const int nb1 = (wq >> 1) * 32;
    // stage2 warp tiling: 4 m-tiles (c) x 2 n-tiles (k)
    const int mb2 = wq & 3;
    const int nb2 = (wq >> 2) * 32;

    __syncthreads();  // bias/W visible
    float bl[2], bh[2];
#pragma unroll
    for (int mi = 0; mi < 2; ++mi) {
        bl[mi] = bs[32 * mb1 + 16 * mi + g];
        bh[mi] = bs[32 * mb1 + 16 * mi + g + 8];
    }

    float accv[2][4][4];
#pragma unroll
    for (int mi = 0; mi < 2; ++mi)
#pragma unroll
        for (int t = 0; t < 4; ++t)
#pragma unroll
            for (int i = 0; i < 4; ++i) accv[mi][t][i] = 0.0f;

    float asum_loc = 0.0f;

    for (int ch = 0; ch < NCHUNK; ++ch) {
        const float* Xc = smf + (ch & 1 ? X1_OFF : X0_OFF);

        // issue copy of chunk ch+1 into the other buffer, then wait for ch
        if (ch + 1 < NCHUNK) {
            uint32_t dst = xbuf_u32[(ch + 1) & 1];
            const float* src = xg + (ch + 1) * PT;
#pragma unroll
            for (int j = 0; j < 16; ++j) {
                int i = tid + 256 * j;
                int c = i >> 5, s16 = i & 31;
                cp_async16(dst + (uint32_t)(c * SLX * 4 + s16 * 16),
                           src + (size_t)c * PP + s16 * 4);
            }
            cp_commit();
            cp_wait<1>();   // chunk ch complete, ch+1 in flight
        } else {
            cp_wait<0>();
        }
        __syncthreads();    // copies visible to all threads; As free from ch-1

        // ---- stage1: logits[k][p] = W @ x  (K = c, 16 k8-steps) ----
        {
            float acc1[2][4][4];
#pragma unroll
            for (int mi = 0; mi < 2; ++mi)
#pragma unroll
                for (int t = 0; t < 4; ++t) {
                    acc1[mi][t][0] = bl[mi]; acc1[mi][t][1] = bl[mi];
                    acc1[mi][t][2] = bh[mi]; acc1[mi][t][3] = bh[mi];
                }
            const float* wb = Ws + (32 * mb1 + g) * SLW + m;
#pragma unroll 4
            for (int Ks = 0; Ks < 16; ++Ks) {
                uint32_t aA[2][4];
#pragma unroll
                for (int mi = 0; mi < 2; ++mi) {
                    const float* wp = wb + mi * 16 * SLW + 8 * Ks;
                    aA[mi][0] = f2u(wp[0]);
                    aA[mi][1] = f2u(wp[8 * SLW]);
                    aA[mi][2] = f2u(wp[4]);
                    aA[mi][3] = f2u(wp[8 * SLW + 4]);
                }
                const float* xb = Xc + (8 * Ks + m) * SLX + nb1 + g;
#pragma unroll
                for (int t = 0; t < 4; ++t) {
                    uint32_t b0 = f2u(xb[8 * t]);
                    uint32_t b1 = f2u(xb[4 * SLX + 8 * t]);
                    mma8(acc1[0][t], aA[0][0], aA[0][1], aA[0][2], aA[0][3], b0, b1);
                    mma8(acc1[1][t], aA[1][0], aA[1][1], aA[1][2], aA[1][3], b0, b1);
                }
            }
#pragma unroll
            for (int mi = 0; mi < 2; ++mi) {
                float* lb = As + (32 * mb1 + 16 * mi + g) * SLA + nb1 + 2 * m;
#pragma unroll
                for (int t = 0; t < 4; ++t) {
                    *(float2*)(lb + 8 * t) =
                        make_float2(acc1[mi][t][0], acc1[mi][t][1]);
                    *(float2*)(lb + 8 * SLA + 8 * t) =
                        make_float2(acc1[mi][t][2], acc1[mi][t][3]);
                }
            }
        }
        __syncthreads();

        // ---- softmax over k, in place (2 threads per pixel) ----
        {
            int p = tid & 127, h = tid >> 7, k0 = h << 5;
            float l[32], mx = -1e30f;
#pragma unroll
            for (int j = 0; j < 32; ++j) {
                l[j] = As[(k0 + j) * SLA + p];
                mx = fmaxf(mx, l[j]);
            }
            redm[h * PT + p] = mx;
            __syncthreads();
            float M = fmaxf(redm[p], redm[PT + p]);
            float s = 0.0f;
#pragma unroll
            for (int j = 0; j < 32; ++j) {
                l[j] = __expf(l[j] - M);
                s += l[j];
            }
            reds[h * PT + p] = s;
            __syncthreads();
            float inv = 1.0f / (reds[p] + reds[PT + p]);
#pragma unroll
            for (int j = 0; j < 32; ++j)
                As[(k0 + j) * SLA + p] = to_tf32(l[j] * inv);
        }
        __syncthreads();

        // ---- asum[k]: warps 0-1, conflict-free float4 row reads ----
        if (tid < KK) {
            const float4* ap = (const float4*)(As + tid * SLA);
            float s = 0.0f;
#pragma unroll
            for (int j = 0; j < 32; ++j) {
                float4 v = ap[j];
                s += (v.x + v.y) + (v.z + v.w);
            }
            asum_loc += s;
        }

        // ---- stage2: vlad[c][k] += x @ a^T  (K = p, 16 k8-steps) ----
        {
            const float* xb = Xc + (32 * mb2 + g) * SLX + m;
            const float* ab = As + (nb2 + g) * SLA + m;
#pragma unroll 4
            for (int Ks = 0; Ks < 16; ++Ks) {
                uint32_t aX[2][4];
#pragma unroll
                for (int mi = 0; mi < 2; ++mi) {
                    const float* xp = xb + mi * 16 * SLX + 8 * Ks;
                    aX[mi][0] = f2u(xp[0]);
                    aX[mi][1] = f2u(xp[8 * SLX]);
                    aX[mi][2] = f2u(xp[4]);
                    aX[mi][3] = f2u(xp[8 * SLX + 4]);
                }
#pragma unroll
                for (int t = 0; t < 4; ++t) {
                    uint32_t b0 = f2u(ab[8 * t * SLA + 8 * Ks]);
                    uint32_t b1 = f2u(ab[8 * t * SLA + 8 * Ks + 4]);
                    mma8(accv[0][t], aX[0][0], aX[0][1], aX[0][2], aX[0][3], b0, b1);
                    mma8(accv[1][t], aX[1][0], aX[1][1], aX[1][2], aX[1][3], b0, b1);
                }
            }
        }
        __syncthreads();   // stage2 done reading Xc before its buffer is refilled
    }

    // ---- epilogue ----
    float* dst = g_vacc + (size_t)(n * HALVES + half) * KK * CC;
#pragma unroll
    for (int mi = 0; mi < 2; ++mi) {
#pragma unroll
        for (int t = 0; t < 4; ++t) {
            int c = 32 * mb2 + 16 * mi + g;
            int k = nb2 + 8 * t + 2 * m;
            dst[k * CC + c]           = accv[mi][t][0];
            dst[(k + 1) * CC + c]     = accv[mi][t][1];
            dst[k * CC + c + 8]       = accv[mi][t][2];
            dst[(k + 1) * CC + c + 8] = accv[mi][t][3];
        }
    }
    if (tid < KK)
        g_sacc[(n * HALVES + half) * KK + tid] = asum_loc;
}

// ---------------- finalize A: per-(n,k) subtract + intra-norm ----------------
// grid (8, 64): blockIdx.y = n, blockIdx.x = 8-k group; 8 warps = 8 k each.
__global__ __launch_bounds__(256)
void netvlad_final_a(const float* __restrict__ cent) {
    int n = blockIdx.y, kb = blockIdx.x;
    int lane = threadIdx.x & 31, warp = threadIdx.x >> 5;
    int k = kb * 8 + warp;

    float as = g_sacc[(n * HALVES + 0) * KK + k] +
               g_sacc[(n * HALVES + 1) * KK + k];

    const float* v0 = g_vacc + (size_t)(n * HALVES + 0) * KK * CC + k * CC;
    const float* v1 = g_vacc + (size_t)(n * HALVES + 1) * KK * CC + k * CC;
    float4 a0 = *(const float4*)(v0 + 4 * lane);
    float4 a1 = *(const float4*)(v1 + 4 * lane);
    float4 ce = *(const float4*)(cent + k * CC + 4 * lane);

    float w0 = a0.x + a1.x - as * ce.x;
    float w1 = a0.y + a1.y - as * ce.y;
    float w2 = a0.z + a1.z - as * ce.z;
    float w3 = a0.w + a1.w - as * ce.w;
    float ssq = w0 * w0 + w1 * w1 + w2 * w2 + w3 * w3;
#pragma unroll
    for (int o = 16; o; o >>= 1) ssq += __shfl_xor_sync(0xffffffffu, ssq, o);
    float rn = 1.0f / fmaxf(sqrtf(ssq), 1e-12f);

    // write intra-normalized y in place of half-0 accumulator
    float* y = g_vacc + (size_t)(n * HALVES + 0) * KK * CC + k * CC;
    *(float4*)(y + 4 * lane) = make_float4(w0 * rn, w1 * rn, w2 * rn, w3 * rn);
    if (lane == 0) g_ssq[n * KK + k] = ssq * rn * rn;  // = 1 if ssq>eps
}

// ---------------- finalize B: global L2 norm + store -------------------------
// grid (4, 64): blockIdx.y = n, blockIdx.x = quarter of the 8192-float vector.
__global__ __launch_bounds__(256)
void netvlad_final_b(float* __restrict__ out) {
    int n = blockIdx.y, q = blockIdx.x;
    int lane = threadIdx.x & 31;

    // every warp independently sums the 64 per-k ssq values
    float s = g_ssq[n * KK + lane] + g_ssq[n * KK + 32 + lane];
#pragma unroll
    for (int o = 16; o; o >>= 1) s += __shfl_xor_sync(0xffffffffu, s, o);
    float rg = 1.0f / fmaxf(sqrtf(s), 1e-12f);

    const float* y = g_vacc + (size_t)(n * HALVES + 0) * KK * CC + q * 2048;
    float* o4 = out + (size_t)n * KK * CC + q * 2048;
#pragma unroll
    for (int j = 0; j < 2; ++j) {
        int idx = (threadIdx.x + 256 * j) * 4;
        float4 v = *(const float4*)(y + idx);
        *(float4*)(o4 + idx) =
            make_float4(v.x * rg, v.y * rg, v.z * rg, v.w * rg);
    }
}

extern "C" void kernel_launch(void* const* d_in, const int* in_sizes, int n_in,
                              void* d_out, int out_size) {
    const float* x    = (const float*)d_in[0];
    const float* w    = (const float*)d_in[1];
    const float* b    = (const float*)d_in[2];
    const float* cent = (const float*)d_in[3];
    float* out = (float*)d_out;
    (void)in_sizes; (void)n_in; (void)out_size;

    cudaFuncSetAttribute(netvlad_main, cudaFuncAttributeMaxDynamicSharedMemorySize,
                         SMEM_BYTES);

    netvlad_main<<<dim3(HALVES, NN), 256, SMEM_BYTES>>>(x, w, b);
    netvlad_final_a<<<dim3(8, NN), 256>>>(cent);
    netvlad_final_b<<<dim3(4, NN), 256>>>(out);
}

// round 14
// speedup vs baseline: 4.4088x; 1.3209x over previous
#include <cuda_runtime.h>
#include <cuda_fp16.h>
#include <cstdint>
#include <math.h>

// ---------------- problem constants ----------------
#define NN 64
#define CC 128          // channels
#define KK 64           // clusters
#define PP 4096         // pixels per image
#define PT 128          // pixels per chunk
#define QQ 4            // quarters of the pixel dim
#define P_QTR (PP / QQ)           // 1024
#define NCHUNK (P_QTR / PT)       // 8

// word strides (32-bit words) — bank-conflict audited
#define SWW 68    // W  [k][c-halves]: 68%32=4  -> lanes 4g+m unique
#define SWA 68    // Xa [c][p-halves]: 68%32=4  -> lanes 4g+m unique
#define SWB 136   // Xb [c2][p-half2]: 136%32=8 -> lanes 8m+g unique
#define SWS 68    // As [k][p-halves]: 68%32=4  -> stage2-B 4g+m; softmax q-lanes unique

// smem layout (byte offsets, all 16B aligned)
#define W_B    0                         // 64*68*4  = 17408
#define AS_B   17408                     // 64*68*4  = 17408
#define XA_B   34816                     // 128*68*4 = 34816
#define XB_B   69632                     // 64*136*4 = 34816
#define RED_B  104448                    // redm/reds float2[4][64] x2 = 4096
#define BIAS_B 108544                    // 64*4 = 256
#define SMEM_BYTES 108800

// ---------------- scratch (device globals: no cudaMalloc) ----------------
__device__ float g_vacc[NN * QQ * KK * CC];  // 8 MB
__device__ float g_sacc[NN * QQ * KK];
__device__ float g_ssq[NN * KK];

// ---------------- helpers ----------------
// m16n8k16 f16 MMA, f32 accum. Fragment layout (PTX doc, g=lane>>2, m=lane&3):
//   A (16x16 row-major): a0=(g,2m:2m+1) a1=(g+8,2m:2m+1) a2=(g,2m+8:2m+9) a3=(g+8,2m+8:2m+9)
//   B (16x8  col-major): b0=(2m:2m+1, g) b1=(2m+8:2m+9, g)
//   D: c0=(g,2m) c1=(g,2m+1) c2=(g+8,2m) c3=(g+8,2m+1)
__device__ __forceinline__ void mma16(float d[4], uint32_t a0, uint32_t a1,
                                      uint32_t a2, uint32_t a3,
                                      uint32_t b0, uint32_t b1) {
    asm volatile(
        "mma.sync.aligned.m16n8k16.row.col.f32.f16.f16.f32 "
        "{%0,%1,%2,%3}, {%4,%5,%6,%7}, {%8,%9}, {%0,%1,%2,%3};"
        : "+f"(d[0]), "+f"(d[1]), "+f"(d[2]), "+f"(d[3])
        : "r"(a0), "r"(a1), "r"(a2), "r"(a3), "r"(b0), "r"(b1));
}

__device__ __forceinline__ uint32_t packh2(float lo, float hi) {
    __half2 h = __floats2half2_rn(lo, hi);
    return *reinterpret_cast<uint32_t*>(&h);
}
__device__ __forceinline__ float2 unpackh2(uint32_t u) {
    __half2 h = *reinterpret_cast<__half2*>(&u);
    return __half22float2(h);
}

// ---------------- main fused kernel ----------------
// grid (QQ, NN), 256 threads, 2 CTAs/SM.
__global__ __launch_bounds__(256, 2)
void netvlad_main(const float* __restrict__ x,
                  const float* __restrict__ w,
                  const float* __restrict__ bias) {
    extern __shared__ __align__(16) char smb[];
    uint32_t* Ws2 = (uint32_t*)(smb + W_B);
    uint32_t* As2 = (uint32_t*)(smb + AS_B);
    uint32_t* Xa2 = (uint32_t*)(smb + XA_B);
    uint32_t* Xb2 = (uint32_t*)(smb + XB_B);
    float2*   redm = (float2*)(smb + RED_B);           // [4][64]
    float2*   reds = (float2*)(smb + RED_B + 2048);    // [4][64]
    float*    bs   = (float*)(smb + BIAS_B);

    const int tid = threadIdx.x, lane = tid & 31, wq = tid >> 5;
    const int g = lane >> 2, m = lane & 3;
    const int n = blockIdx.y, qtr = blockIdx.x;

    // ---- load W as fp16 word-packed [k][c/2] + bias ----
    for (int i = tid; i < KK * CC / 2; i += 256) {
        int k = i >> 6, c2 = i & 63;
        Ws2[k * SWW + c2] = packh2(w[k * CC + 2 * c2], w[k * CC + 2 * c2 + 1]);
    }
    if (tid < KK) bs[tid] = bias[tid];

    // stage1 warp tiling: 2 m-tiles (k) x 4 n-tiles (p)
    const int mb1 = wq & 1;
    const int nb1 = (wq >> 1) * 32;
    // stage2 warp tiling: 4 m-tiles (c) x 2 n-tiles (k)
    const int mb2 = wq & 3;
    const int nb2 = (wq >> 2) * 32;

    __syncthreads();
    float bl[2], bh[2];
#pragma unroll
    for (int mi = 0; mi < 2; ++mi) {
        bl[mi] = bs[32 * mb1 + 16 * mi + g];
        bh[mi] = bs[32 * mb1 + 16 * mi + g + 8];
    }

    float accv[2][4][4];
#pragma unroll
    for (int mi = 0; mi < 2; ++mi)
#pragma unroll
        for (int t = 0; t < 4; ++t)
#pragma unroll
            for (int i = 0; i < 4; ++i) accv[mi][t][i] = 0.0f;

    float asum_loc = 0.0f;

    const float* xg = x + (size_t)n * CC * PP + (size_t)qtr * P_QTR;

    for (int ch = 0; ch < NCHUNK; ++ch) {
        __syncthreads();  // prev stage2 done reading Xa/Xb/As

        // ---- stage chunk: gmem fp32 -> Xa (plain fp16) + Xb (c-paired half2) ----
        {
            const float* xc = xg + ch * PT;
#pragma unroll
            for (int j = 0; j < 8; ++j) {
                int i = tid + 256 * j;
                int c2 = i >> 5, p4 = (i & 31) << 2;
                float4 r0 = *(const float4*)(xc + (size_t)(2 * c2) * PP + p4);
                float4 r1 = *(const float4*)(xc + (size_t)(2 * c2 + 1) * PP + p4);
                // Xa: two rows, 2 halves per word over p
                uint2 w0 = make_uint2(packh2(r0.x, r0.y), packh2(r0.z, r0.w));
                uint2 w1 = make_uint2(packh2(r1.x, r1.y), packh2(r1.z, r1.w));
                *(uint2*)(Xa2 + (2 * c2) * SWA + (p4 >> 1)) = w0;
                *(uint2*)(Xa2 + (2 * c2 + 1) * SWA + (p4 >> 1)) = w1;
                // Xb: c-pairs per word, one word per p
                uint4 wb = make_uint4(packh2(r0.x, r1.x), packh2(r0.y, r1.y),
                                      packh2(r0.z, r1.z), packh2(r0.w, r1.w));
                *(uint4*)(Xb2 + c2 * SWB + p4) = wb;
            }
        }
        __syncthreads();

        // ---- stage1: logits[k][p] = W @ x  (K = c = 128, 8 k16-steps) ----
        {
            float acc1[2][4][4];
#pragma unroll
            for (int mi = 0; mi < 2; ++mi)
#pragma unroll
                for (int t = 0; t < 4; ++t) {
                    acc1[mi][t][0] = bl[mi]; acc1[mi][t][1] = bl[mi];
                    acc1[mi][t][2] = bh[mi]; acc1[mi][t][3] = bh[mi];
                }
#pragma unroll
            for (int Ks = 0; Ks < 8; ++Ks) {
                uint32_t aA[2][4];
#pragma unroll
                for (int mi = 0; mi < 2; ++mi) {
                    int row = (32 * mb1 + 16 * mi + g) * SWW + 8 * Ks + m;
                    aA[mi][0] = Ws2[row];
                    aA[mi][1] = Ws2[row + 8 * SWW];
                    aA[mi][2] = Ws2[row + 4];
                    aA[mi][3] = Ws2[row + 8 * SWW + 4];
                }
#pragma unroll
                for (int t = 0; t < 4; ++t) {
                    int pcol = nb1 + 8 * t + g;
                    uint32_t b0 = Xb2[(8 * Ks + m) * SWB + pcol];
                    uint32_t b1 = Xb2[(8 * Ks + m + 4) * SWB + pcol];
                    mma16(acc1[0][t], aA[0][0], aA[0][1], aA[0][2], aA[0][3], b0, b1);
                    mma16(acc1[1][t], aA[1][0], aA[1][1], aA[1][2], aA[1][3], b0, b1);
                }
            }
            // store logits as half2 words: word col = nb1/2 + 4t + m
#pragma unroll
            for (int mi = 0; mi < 2; ++mi) {
                int row = (32 * mb1 + 16 * mi + g) * SWS + (nb1 >> 1);
#pragma unroll
                for (int t = 0; t < 4; ++t) {
                    As2[row + 4 * t + m] = packh2(acc1[mi][t][0], acc1[mi][t][1]);
                    As2[row + 8 * SWS + 4 * t + m] = packh2(acc1[mi][t][2], acc1[mi][t][3]);
                }
            }
        }
        __syncthreads();

        // ---- softmax over k: thread = (word-col q in [0,64), k-group h in [0,4)) ----
        // Each thread: 16 k values x 2 pixels (one half2 word column).
        {
            int q = tid & 63, h = tid >> 6, k0 = h << 4;
            uint32_t v[16];
            float2 mx = make_float2(-1e30f, -1e30f);
#pragma unroll
            for (int j = 0; j < 16; ++j) {
                v[j] = As2[(k0 + j) * SWS + q];
                float2 f = unpackh2(v[j]);
                mx.x = fmaxf(mx.x, f.x); mx.y = fmaxf(mx.y, f.y);
            }
            redm[h * 64 + q] = mx;
            __syncthreads();
            float2 m0 = redm[q], m1 = redm[64 + q];
            float2 m2 = redm[128 + q], m3 = redm[192 + q];
            float2 M = make_float2(fmaxf(fmaxf(m0.x, m1.x), fmaxf(m2.x, m3.x)),
                                   fmaxf(fmaxf(m0.y, m1.y), fmaxf(m2.y, m3.y)));
            float2 s = make_float2(0.0f, 0.0f);
#pragma unroll
            for (int j = 0; j < 16; ++j) {
                float2 f = unpackh2(v[j]);
                float e0 = __expf(f.x - M.x), e1 = __expf(f.y - M.y);
                s.x += e0; s.y += e1;
                v[j] = packh2(e0, e1);
            }
            reds[h * 64 + q] = s;
            __syncthreads();
            float2 s0 = reds[q], s1 = reds[64 + q];
            float2 s2 = reds[128 + q], s3 = reds[192 + q];
            float2 inv = make_float2(1.0f / ((s0.x + s1.x) + (s2.x + s3.x)),
                                     1.0f / ((s0.y + s1.y) + (s2.y + s3.y)));
#pragma unroll
            for (int j = 0; j < 16; ++j) {
                float2 f = unpackh2(v[j]);
                As2[(k0 + j) * SWS + q] = packh2(f.x * inv.x, f.y * inv.y);
            }
        }
        __syncthreads();

        // ---- asum[k]: warps 0-1, LDS.128 row reads, fp32 accumulate ----
        if (tid < KK) {
            const uint4* ap = (const uint4*)(As2 + tid * SWS);
            float s = 0.0f;
#pragma unroll
            for (int j = 0; j < 16; ++j) {
                uint4 u = ap[j];
                float2 f0 = unpackh2(u.x), f1 = unpackh2(u.y);
                float2 f2 = unpackh2(u.z), f3 = unpackh2(u.w);
                s += (f0.x + f0.y) + (f1.x + f1.y) + (f2.x + f2.y) + (f3.x + f3.y);
            }
            asum_loc += s;
        }

        // ---- stage2: vlad[c][k] += x @ a^T  (K = p = 128, 8 k16-steps) ----
        {
#pragma unroll
            for (int Ks = 0; Ks < 8; ++Ks) {
                uint32_t aX[2][4];
#pragma unroll
                for (int mi = 0; mi < 2; ++mi) {
                    int row = (32 * mb2 + 16 * mi + g) * SWA + 8 * Ks + m;
                    aX[mi][0] = Xa2[row];
                    aX[mi][1] = Xa2[row + 8 * SWA];
                    aX[mi][2] = Xa2[row + 4];
                    aX[mi][3] = Xa2[row + 8 * SWA + 4];
                }
#pragma unroll
                for (int t = 0; t < 4; ++t) {
                    int krow = (nb2 + 8 * t + g) * SWS + 8 * Ks;
                    uint32_t b0 = As2[krow + m];
                    uint32_t b1 = As2[krow + m + 4];
                    mma16(accv[0][t], aX[0][0], aX[0][1], aX[0][2], aX[0][3], b0, b1);
                    mma16(accv[1][t], aX[1][0], aX[1][1], aX[1][2], aX[1][3], b0, b1);
                }
            }
        }
    }

    // ---- epilogue: write vlad partials + asum ----
    float* dst = g_vacc + (size_t)(n * QQ + qtr) * KK * CC;
#pragma unroll
    for (int mi = 0; mi < 2; ++mi) {
#pragma unroll
        for (int t = 0; t < 4; ++t) {
            int c = 32 * mb2 + 16 * mi + g;
            int k = nb2 + 8 * t + 2 * m;
            dst[k * CC + c]           = accv[mi][t][0];
            dst[(k + 1) * CC + c]     = accv[mi][t][1];
            dst[k * CC + c + 8]       = accv[mi][t][2];
            dst[(k + 1) * CC + c + 8] = accv[mi][t][3];
        }
    }
    if (tid < KK)
        g_sacc[(n * QQ + qtr) * KK + tid] = asum_loc;
}

// ---------------- finalize A: per-(n,k) subtract + intra-norm ----------------
__global__ __launch_bounds__(256)
void netvlad_final_a(const float* __restrict__ cent) {
    int n = blockIdx.y, kb = blockIdx.x;
    int lane = threadIdx.x & 31, warp = threadIdx.x >> 5;
    int k = kb * 8 + warp;

    float as = 0.0f;
#pragma unroll
    for (int q = 0; q < QQ; ++q) as += g_sacc[(n * QQ + q) * KK + k];

    float4 acc = make_float4(0.f, 0.f, 0.f, 0.f);
#pragma unroll
    for (int q = 0; q < QQ; ++q) {
        const float4 v = *(const float4*)(g_vacc +
            (size_t)(n * QQ + q) * KK * CC + k * CC + 4 * lane);
        acc.x += v.x; acc.y += v.y; acc.z += v.z; acc.w += v.w;
    }
    float4 ce = *(const float4*)(cent + k * CC + 4 * lane);
    float w0 = acc.x - as * ce.x;
    float w1 = acc.y - as * ce.y;
    float w2 = acc.z - as * ce.z;
    float w3 = acc.w - as * ce.w;
    float ssq = w0 * w0 + w1 * w1 + w2 * w2 + w3 * w3;
#pragma unroll
    for (int o = 16; o; o >>= 1) ssq += __shfl_xor_sync(0xffffffffu, ssq, o);
    float rn = 1.0f / fmaxf(sqrtf(ssq), 1e-12f);

    float* y = g_vacc + (size_t)(n * QQ + 0) * KK * CC + k * CC;
    *(float4*)(y + 4 * lane) = make_float4(w0 * rn, w1 * rn, w2 * rn, w3 * rn);
    if (lane == 0) g_ssq[n * KK + k] = ssq * rn * rn;
}

// ---------------- finalize B: global L2 norm + store -------------------------
__global__ __launch_bounds__(256)
void netvlad_final_b(float* __restrict__ out) {
    int n = blockIdx.y, q = blockIdx.x;
    int lane = threadIdx.x & 31;

    float s = g_ssq[n * KK + lane] + g_ssq[n * KK + 32 + lane];
#pragma unroll
    for (int o = 16; o; o >>= 1) s += __shfl_xor_sync(0xffffffffu, s, o);
    float rg = 1.0f / fmaxf(sqrtf(s), 1e-12f);

    const float* y = g_vacc + (size_t)(n * QQ + 0) * KK * CC + q * 2048;
    float* o4 = out + (size_t)n * KK * CC + q * 2048;
#pragma unroll
    for (int j = 0; j < 2; ++j) {
        int idx = (threadIdx.x + 256 * j) * 4;
        float4 v = *(const float4*)(y + idx);
        *(float4*)(o4 + idx) =
            make_float4(v.x * rg, v.y * rg, v.z * rg, v.w * rg);
    }
}

extern "C" void kernel_launch(void* const* d_in, const int* in_sizes, int n_in,
                              void* d_out, int out_size) {
    const float* x    = (const float*)d_in[0];
    const float* w    = (const float*)d_in[1];
    const float* b    = (const float*)d_in[2];
    const float* cent = (const float*)d_in[3];
    float* out = (float*)d_out;
    (void)in_sizes; (void)n_in; (void)out_size;

    cudaFuncSetAttribute(netvlad_main, cudaFuncAttributeMaxDynamicSharedMemorySize,
                         SMEM_BYTES);

    netvlad_main<<<dim3(QQ, NN), 256, SMEM_BYTES>>>(x, w, b);
    netvlad_final_a<<<dim3(8, NN), 256>>>(cent);
    netvlad_final_b<<<dim3(4, NN), 256>>>(out);
}

// round 17
// speedup vs baseline: 4.9008x; 1.1116x over previous
#include <cuda_runtime.h>
#include <cuda_fp16.h>
#include <cstdint>
#include <math.h>

// ---------------- problem constants ----------------
#define NN 64
#define CC 128          // channels
#define KK 64           // clusters
#define PP 4096         // pixels per image
#define PT 128          // pixels per chunk
#define QQ 8            // slices of the pixel dim (512 CTAs -> good balance)
#define P_QTR (PP / QQ)           // 512
#define NCHUNK (P_QTR / PT)       // 4
#define LOG2E 1.4426950408889634f

// word strides (32-bit words) — bank-conflict audited (68%32=4)
#define SWW 68    // W  [k][c-halves]
#define SWA 68    // Xa [c][p-halves]
#define SWS 68    // As [k][p-halves]

// smem layout (byte offsets, 16B aligned)
#define W_B    0                         // 64*68*4  = 17408
#define AS_B   17408                     // 64*68*4  = 17408
#define XA_B   34816                     // 128*68*4 = 34816
#define RED_B  69632                     // reds float2[4][64] = 2048
#define BIAS_B 71680                     // 256
#define SMEM_BYTES 71936

// ---------------- scratch (device globals: no cudaMalloc) ----------------
__device__ float g_vacc[NN * QQ * KK * CC];  // 16 MB
__device__ float g_sacc[NN * QQ * KK];
__device__ float g_ssq[NN * KK];

// ---------------- helpers ----------------
__device__ __forceinline__ uint32_t smem_u32(const void* p) {
    uint32_t a;
    asm("{ .reg .u64 t; cvta.to.shared.u64 t, %1; cvt.u32.u64 %0, t; }"
        : "=r"(a) : "l"(p));
    return a;
}
__device__ __forceinline__ void ldmx4(uint32_t r[4], uint32_t addr) {
    asm volatile("ldmatrix.sync.aligned.m8n8.x4.shared.b16 {%0,%1,%2,%3}, [%4];"
                 : "=r"(r[0]), "=r"(r[1]), "=r"(r[2]), "=r"(r[3]) : "r"(addr));
}
__device__ __forceinline__ void ldmx4t(uint32_t r[4], uint32_t addr) {
    asm volatile("ldmatrix.sync.aligned.m8n8.x4.trans.shared.b16 {%0,%1,%2,%3}, [%4];"
                 : "=r"(r[0]), "=r"(r[1]), "=r"(r[2]), "=r"(r[3]) : "r"(addr));
}
// m16n8k16 f16 MMA, f32 accum (fragment model verified by passing Round 14)
__device__ __forceinline__ void mma16(float d[4], uint32_t a0, uint32_t a1,
                                      uint32_t a2, uint32_t a3,
                                      uint32_t b0, uint32_t b1) {
    asm volatile(
        "mma.sync.aligned.m16n8k16.row.col.f32.f16.f16.f32 "
        "{%0,%1,%2,%3}, {%4,%5,%6,%7}, {%8,%9}, {%0,%1,%2,%3};"
        : "+f"(d[0]), "+f"(d[1]), "+f"(d[2]), "+f"(d[3])
        : "r"(a0), "r"(a1), "r"(a2), "r"(a3), "r"(b0), "r"(b1));
}
__device__ __forceinline__ uint32_t packh2(float lo, float hi) {
    __half2 h = __floats2half2_rn(lo, hi);
    return *reinterpret_cast<uint32_t*>(&h);
}
__device__ __forceinline__ float2 unpackh2(uint32_t u) {
    __half2 h = *reinterpret_cast<__half2*>(&u);
    return __half22float2(h);
}

// ---------------- main fused kernel ----------------
// grid (QQ, NN), 256 threads, 2 CTAs/SM.
__global__ __launch_bounds__(256, 2)
void netvlad_main(const float* __restrict__ x,
                  const float* __restrict__ w,
                  const float* __restrict__ bias) {
    extern __shared__ __align__(16) char smb[];
    uint32_t* Ws2 = (uint32_t*)(smb + W_B);
    uint32_t* As2 = (uint32_t*)(smb + AS_B);
    uint32_t* Xa2 = (uint32_t*)(smb + XA_B);
    float2*   reds = (float2*)(smb + RED_B);   // [4][64]
    float*    bs   = (float*)(smb + BIAS_B);

    const int tid = threadIdx.x, lane = tid & 31, wq = tid >> 5;
    const int g = lane >> 2, m = lane & 3;
    const int n = blockIdx.y, qtr = blockIdx.x;
    const uint32_t sb = smem_u32(smb);

    // ---- load W (fp16, pre-scaled by log2e) + bias ----
    for (int i = tid; i < KK * CC / 2; i += 256) {
        int k = i >> 6, c2 = i & 63;
        Ws2[k * SWW + c2] = packh2(w[k * CC + 2 * c2] * LOG2E,
                                   w[k * CC + 2 * c2 + 1] * LOG2E);
    }
    if (tid < KK) bs[tid] = bias[tid] * LOG2E;

    // warp tilings
    const int mb1 = wq & 1;            // stage1 k block
    const int nb1 = (wq >> 1) * 32;    // stage1 p block
    const int mb2 = wq & 3;            // stage2 c block
    const int nb2 = (wq >> 2) * 32;    // stage2 k block

    // ldmatrix per-lane address components
    const int blk = lane >> 3, lr = lane & 7;
    const int arow  = (blk & 1) * 8 + lr;   // non-trans A row-in-tile
    const int acolw = (blk >> 1) * 4;       // non-trans A word col-in-tile
    // stage1 A bases (Ws), per mi; advance +32B per Ks
    uint32_t s1a[2];
#pragma unroll
    for (int mi = 0; mi < 2; ++mi)
        s1a[mi] = sb + W_B + (uint32_t)(((32 * mb1 + 16 * mi + arow) * SWW + acolw) * 4);
    // stage1 B base (Xa, trans): rows = c (16/Ks), cols = p words; advance +16*SWA*4
    const uint32_t s1b0 = sb + XA_B + (uint32_t)((lr * SWA + (nb1 >> 1) + blk * 4) * 4);
    // stage2 A bases (Xa); advance +32B per Ks
    uint32_t s2a[2];
#pragma unroll
    for (int mi = 0; mi < 2; ++mi)
        s2a[mi] = sb + XA_B + (uint32_t)(((32 * mb2 + 16 * mi + arow) * SWA + acolw) * 4);
    // stage2 B base (As, NON-trans: K=p is contiguous in As rows); advance +32B per Ks
    const uint32_t s2b0 = sb + AS_B + (uint32_t)(((nb2 + blk * 8 + lr) * SWS) * 4);

    __syncthreads();
    float bl[2], bh[2];
#pragma unroll
    for (int mi = 0; mi < 2; ++mi) {
        bl[mi] = bs[32 * mb1 + 16 * mi + g];
        bh[mi] = bs[32 * mb1 + 16 * mi + g + 8];
    }

    float accv[2][4][4];
#pragma unroll
    for (int mi = 0; mi < 2; ++mi)
#pragma unroll
        for (int t = 0; t < 4; ++t)
#pragma unroll
            for (int i = 0; i < 4; ++i) accv[mi][t][i] = 0.0f;

    float asum_loc = 0.0f;
    const float* xg = x + (size_t)n * CC * PP + (size_t)qtr * P_QTR;

    for (int ch = 0; ch < NCHUNK; ++ch) {
        __syncthreads();  // prev stage2 done reading Xa/As

        // ---- stage chunk: gmem fp32 -> Xa fp16 [c][p-halves] ----
        {
            const float* xc = xg + ch * PT;
#pragma unroll
            for (int j = 0; j < 16; ++j) {
                int i = tid + 256 * j;
                int c = i >> 5, p4 = (i & 31) << 2;
                float4 v = *(const float4*)(xc + (size_t)c * PP + p4);
                *(uint2*)(Xa2 + c * SWA + (p4 >> 1)) =
                    make_uint2(packh2(v.x, v.y), packh2(v.z, v.w));
            }
        }
        __syncthreads();

        // ---- stage1: logits (log2-scaled) = W' @ x, via ldmatrix ----
        {
            float acc1[2][4][4];
#pragma unroll
            for (int mi = 0; mi < 2; ++mi)
#pragma unroll
                for (int t = 0; t < 4; ++t) {
                    acc1[mi][t][0] = bl[mi]; acc1[mi][t][1] = bl[mi];
                    acc1[mi][t][2] = bh[mi]; acc1[mi][t][3] = bh[mi];
                }
            uint32_t wa0 = s1a[0], wa1 = s1a[1], xb = s1b0;
#pragma unroll
            for (int Ks = 0; Ks < 8; ++Ks) {
                uint32_t aA0[4], aA1[4], b0r[4], b1r[4];
                ldmx4(aA0, wa0);
                ldmx4(aA1, wa1);
                ldmx4t(b0r, xb);                    // c-rows 0-7  -> b0 for t=0..3
                ldmx4t(b1r, xb + 8 * SWA * 4);      // c-rows 8-15 -> b1
#pragma unroll
                for (int t = 0; t < 4; ++t) {
                    mma16(acc1[0][t], aA0[0], aA0[1], aA0[2], aA0[3], b0r[t], b1r[t]);
                    mma16(acc1[1][t], aA1[0], aA1[1], aA1[2], aA1[3], b0r[t], b1r[t]);
                }
                wa0 += 32; wa1 += 32; xb += 16 * SWA * 4;
            }
            // store logits as half2 words
#pragma unroll
            for (int mi = 0; mi < 2; ++mi) {
                int row = (32 * mb1 + 16 * mi + g) * SWS + (nb1 >> 1);
#pragma unroll
                for (int t = 0; t < 4; ++t) {
                    As2[row + 4 * t + m] = packh2(acc1[mi][t][0], acc1[mi][t][1]);
                    As2[row + 8 * SWS + 4 * t + m] = packh2(acc1[mi][t][2], acc1[mi][t][3]);
                }
            }
        }
        __syncthreads();

        // ---- softmax over k (no max pass; logits in log2 units, exp2) ----
        {
            int q = tid & 63, h = tid >> 6, k0 = h << 4;
            uint32_t v[16];
            float2 s = make_float2(0.0f, 0.0f);
#pragma unroll
            for (int j = 0; j < 16; ++j) {
                v[j] = As2[(k0 + j) * SWS + q];
                float2 f = unpackh2(v[j]);
                float e0 = exp2f(f.x), e1 = exp2f(f.y);
                s.x += e0; s.y += e1;
                v[j] = packh2(e0, e1);
            }
            reds[h * 64 + q] = s;
            __syncthreads();
            float2 s0 = reds[q], s1 = reds[64 + q];
            float2 s2 = reds[128 + q], s3 = reds[192 + q];
            float2 inv = make_float2(1.0f / ((s0.x + s1.x) + (s2.x + s3.x)),
                                     1.0f / ((s0.y + s1.y) + (s2.y + s3.y)));
#pragma unroll
            for (int j = 0; j < 16; ++j) {
                float2 f = unpackh2(v[j]);
                As2[(k0 + j) * SWS + q] = packh2(f.x * inv.x, f.y * inv.y);
            }
        }
        __syncthreads();

        // ---- asum[k]: warps 0-1, LDS.128 row reads, fp32 accumulate ----
        if (tid < KK) {
            const uint4* ap = (const uint4*)(As2 + tid * SWS);
            float s = 0.0f;
#pragma unroll
            for (int j = 0; j < 16; ++j) {
                uint4 u = ap[j];
                float2 f0 = unpackh2(u.x), f1 = unpackh2(u.y);
                float2 f2 = unpackh2(u.z), f3 = unpackh2(u.w);
                s += (f0.x + f0.y) + (f1.x + f1.y) + (f2.x + f2.y) + (f3.x + f3.y);
            }
            asum_loc += s;
        }

        // ---- stage2: vlad[c][k] += x @ a^T, via ldmatrix (B NON-trans) ----
        {
            uint32_t xa0 = s2a[0], xa1 = s2a[1], ab = s2b0;
#pragma unroll
            for (int Ks = 0; Ks < 8; ++Ks) {
                uint32_t aX0[4], aX1[4], bb0[4], bb1[4];
                ldmx4(aX0, xa0);
                ldmx4(aX1, xa1);
                ldmx4(bb0, ab);           // p 16Ks+0..7  -> b0 for t=0..3
                ldmx4(bb1, ab + 16);      // p 16Ks+8..15 -> b1
#pragma unroll
                for (int t = 0; t < 4; ++t) {
                    mma16(accv[0][t], aX0[0], aX0[1], aX0[2], aX0[3], bb0[t], bb1[t]);
                    mma16(accv[1][t], aX1[0], aX1[1], aX1[2], aX1[3], bb0[t], bb1[t]);
                }
                xa0 += 32; xa1 += 32; ab += 32;
            }
        }
    }

    // ---- epilogue: write vlad partials + asum ----
    float* dst = g_vacc + (size_t)(n * QQ + qtr) * KK * CC;
#pragma unroll
    for (int mi = 0; mi < 2; ++mi) {
#pragma unroll
        for (int t = 0; t < 4; ++t) {
            int c = 32 * mb2 + 16 * mi + g;
            int k = nb2 + 8 * t + 2 * m;
            dst[k * CC + c]           = accv[mi][t][0];
            dst[(k + 1) * CC + c]     = accv[mi][t][1];
            dst[k * CC + c + 8]       = accv[mi][t][2];
            dst[(k + 1) * CC + c + 8] = accv[mi][t][3];
        }
    }
    if (tid < KK)
        g_sacc[(n * QQ + qtr) * KK + tid] = asum_loc;
}

// ---------------- finalize A: per-(n,k) subtract + intra-norm ----------------
__global__ __launch_bounds__(256)
void netvlad_final_a(const float* __restrict__ cent) {
    int n = blockIdx.y, kb = blockIdx.x;
    int lane = threadIdx.x & 31, warp = threadIdx.x >> 5;
    int k = kb * 8 + warp;

    float as = 0.0f;
#pragma unroll
    for (int q = 0; q < QQ; ++q) as += g_sacc[(n * QQ + q) * KK + k];

    float4 acc = make_float4(0.f, 0.f, 0.f, 0.f);
#pragma unroll
    for (int q = 0; q < QQ; ++q) {
        const float4 v = *(const float4*)(g_vacc +
            (size_t)(n * QQ + q) * KK * CC + k * CC + 4 * lane);
        acc.x += v.x; acc.y += v.y; acc.z += v.z; acc.w += v.w;
    }
    float4 ce = *(const float4*)(cent + k * CC + 4 * lane);
    float w0 = acc.x - as * ce.x;
    float w1 = acc.y - as * ce.y;
    float w2 = acc.z - as * ce.z;
    float w3 = acc.w - as * ce.w;
    float ssq = w0 * w0 + w1 * w1 + w2 * w2 + w3 * w3;
#pragma unroll
    for (int o = 16; o; o >>= 1) ssq += __shfl_xor_sync(0xffffffffu, ssq, o);
    float rn = 1.0f / fmaxf(sqrtf(ssq), 1e-12f);

    float* y = g_vacc + (size_t)(n * QQ + 0) * KK * CC + k * CC;
    *(float4*)(y + 4 * lane) = make_float4(w0 * rn, w1 * rn, w2 * rn, w3 * rn);
    if (lane == 0) g_ssq[n * KK + k] = ssq * rn * rn;
}

// ---------------- finalize B: global L2 norm + store -------------------------
__global__ __launch_bounds__(256)
void netvlad_final_b(float* __restrict__ out) {
    int n = blockIdx.y, q = blockIdx.x;
    int lane = threadIdx.x & 31;

    float s = g_ssq[n * KK + lane] + g_ssq[n * KK + 32 + lane];
#pragma unroll
    for (int o = 16; o; o >>= 1) s += __shfl_xor_sync(0xffffffffu, s, o);
    float rg = 1.0f / fmaxf(sqrtf(s), 1e-12f);

    const float* y = g_vacc + (size_t)(n * QQ + 0) * KK * CC + q * 2048;
    float* o4 = out + (size_t)n * KK * CC + q * 2048;
#pragma unroll
    for (int j = 0; j < 2; ++j) {
        int idx = (threadIdx.x + 256 * j) * 4;
        float4 v = *(const float4*)(y + idx);
        *(float4*)(o4 + idx) =
            make_float4(v.x * rg, v.y * rg, v.z * rg, v.w * rg);
    }
}

extern "C" void kernel_launch(void* const* d_in, const int* in_sizes, int n_in,
                              void* d_out, int out_size) {
    const float* x    = (const float*)d_in[0];
    const float* w    = (const float*)d_in[1];
    const float* b    = (const float*)d_in[2];
    const float* cent = (const float*)d_in[3];
    float* out = (float*)d_out;
    (void)in_sizes; (void)n_in; (void)out_size;

    cudaFuncSetAttribute(netvlad_main, cudaFuncAttributeMaxDynamicSharedMemorySize,
                         SMEM_BYTES);

    netvlad_main<<<dim3(QQ, NN), 256, SMEM_BYTES>>>(x, w, b);
    netvlad_final_a<<<dim3(8, NN), 256>>>(cent);
    netvlad_final_b<<<dim3(4, NN), 256>>>(out);
}